// round 10
// baseline (speedup 1.0000x reference)
#include <cuda_runtime.h>
#include <cuda_bf16.h>
#include <math.h>

#define BB 4096
#define LL 200
#define FF 8
#define DD 64
#define KK 15
#define GRID_PERSIST 1216   // 152 SMs x 8 resident CTAs
// dynamic smem: per-row partials [200][8] float2 (each = dot/ssq over 8 floats)
#define SMEM_BYTES (LL * 8 * 8)   // 12800 B

__device__ unsigned g_ticket;

__global__ void reset_ticket_kernel() { g_ticket = 0u; }

__device__ __forceinline__ unsigned enc_f(float f) {
    unsigned u = __float_as_uint(f);
    return (u >> 31) ? ~u : (u ^ 0x80000000u);
}
__device__ __forceinline__ float dec_f(unsigned u) {
    unsigned bits = (u & 0x80000000u) ? (u ^ 0x80000000u) : ~u;
    return __uint_as_float(bits);
}

__global__ void __launch_bounds__(256) search_predict_kernel(
    const int* __restrict__ x,        // [B, L, F] int32
    const int* __restrict__ self_loc, // [B] int32
    const float* __restrict__ E,      // [NFEAT+1, D] float32
    float* __restrict__ out)          // [B*16*8] x_out-as-float, then [B*15] sim_topk
{
    extern __shared__ __align__(16) float partials[];   // [200][8] float2, rot-swizzled

    __shared__ __align__(16) float4 selfv[16];          // self embedding row
    __shared__ int catS[LL];
    __shared__ __align__(16) unsigned long long keys[224];
    __shared__ __align__(16) unsigned simk[224];
    __shared__ unsigned long long selKey[KK];
    __shared__ int sortedL[KK + 1];
    __shared__ float invns;
    __shared__ int bad;
    __shared__ int bS;

    const int tid  = threadIdx.x;
    const int warp = tid >> 5;

    while (true) {
        if (tid == 0) { bS = (int)atomicAdd(&g_ticket, 1u); bad = 0; }
        __syncthreads();                 // publishes bS; also fences prev iteration
        const int b = bS;
        if (b >= BB) break;              // uniform across CTA

        const int* xb = x + (size_t)b * (LL * FF);
        const int sl = __ldg(self_loc + b);

        // catS for rows <= sl only; warp 7 loads self row + precomputes inv-norm
        if (tid <= sl) catS[tid] = __ldg(xb + tid * FF + 5);
        if (warp == 7) {
            const int hl = tid & 15;
            if ((tid & 31) < 16) {
                const int cs = __ldg(xb + sl * FF + 5);
                selfv[hl] = __ldg(reinterpret_cast<const float4*>(E + (size_t)cs * DD) + hl);
            }
            __syncwarp();
            const float4 s = selfv[hl];                   // lanes 16-31 mirror 0-15
            float q = s.x * s.x + s.y * s.y + s.z * s.z + s.w * s.w;
            q += __shfl_xor_sync(0xffffffffu, q, 8);
            q += __shfl_xor_sync(0xffffffffu, q, 4);
            q += __shfl_xor_sync(0xffffffffu, q, 2);
            q += __shfl_xor_sync(0xffffffffu, q, 1);
            if (tid == 224) invns = rsqrtf(q + 1e-8f);
        }
        __syncthreads();

        // ---- Phase A: fused gather + partials, ONLY rows l <= sl ----
        {
            const int rg = tid >> 3;          // row within 32-row tile
            const int j8 = tid & 7;           // owns float4 slices j8 and j8+8
            const float4 sa = selfv[j8];
            const float4 sb = selfv[j8 + 8];
            #pragma unroll
            for (int it = 0; it < 7; ++it) {
                const int l = it * 32 + rg;
                if (l <= sl) {                // warp-uniform except one boundary warp
                    const int c = catS[l];
                    const float4* rp = reinterpret_cast<const float4*>(E + (size_t)c * DD);
                    const float4 va = __ldg(rp + j8);
                    const float4 vb = __ldg(rp + j8 + 8);
                    const float dp = va.x*sa.x + va.y*sa.y + va.z*sa.z + va.w*sa.w
                                   + vb.x*sb.x + vb.y*sb.y + vb.z*sb.z + vb.w*sb.w;
                    const float qp = va.x*va.x + va.y*va.y + va.z*va.z + va.w*va.w
                                   + vb.x*vb.x + vb.y*vb.y + vb.z*vb.z + vb.w*vb.w;
                    // rotation swizzle: partial j8 of row l -> 16B chunk ((j8>>1)+(l>>1))&3
                    const int byteoff = l * 64 + ((((j8 >> 1) + (l >> 1)) & 3) << 4)
                                      + ((j8 & 1) << 3);
                    *reinterpret_cast<float2*>(reinterpret_cast<char*>(partials) + byteoff)
                        = make_float2(dp, qp);
                }
            }
        }
        __syncthreads();

        // ---- Phase B: thread-per-row reduction, only rows <= sl ----
        float dot = 0.f, ssq = 0.f;
        if (tid <= sl) {
            const char* base = reinterpret_cast<const char*>(partials) + tid * 64;
            const int rot = (tid >> 1) & 3;
            #pragma unroll
            for (int k = 0; k < 4; ++k) {     // logical chunk order fixed (bit-exact dups)
                const float4 c = *reinterpret_cast<const float4*>(base + (((k + rot) & 3) << 4));
                dot += c.x + c.z;
                ssq += c.y + c.w;
            }
        }
        const float sim = (tid < sl) ? dot * rsqrtf(ssq + 1e-8f) * invns : -2.0f;
        const unsigned e = enc_f(sim);
        const unsigned long long myKey =
            ((unsigned long long)e << 32) | (unsigned)(LL - 1 - tid);
        if (tid < 224) { keys[tid] = myKey; simk[tid] = e; }   // 200..223 pad, inert
        __syncthreads();

        // ---- rank-select among the first sl keys only ----
        int rank = LL;
        if (tid < sl) {
            int r = 0;
            const uint4* p = reinterpret_cast<const uint4*>(simk);
            const int nj = (sl + 3) >> 2;
            for (int j = 0; j < nj; ++j) {            // broadcast LDS.128
                const uint4 k = p[j];
                r += (k.x > e);
                r += (k.y > e);
                r += (k.z > e);
                r += (k.w > e);
            }
            rank = r;
            if (r < KK) selKey[r] = myKey;
        }
        __syncthreads();

        // tie inside top-K -> two threads shared a slot -> loser flags; rare
        if (rank < KK && selKey[rank] != myKey) bad = 1;
        __syncthreads();

        if (bad) {   // exact 64-bit tie-aware recount (keys strictly unique)
            if (tid < sl) {
                int r2 = 0;
                const ulonglong2* k2 = reinterpret_cast<const ulonglong2*>(keys);
                const int nj2 = (sl + 1) >> 1;
                for (int j = 0; j < nj2; ++j) {
                    const ulonglong2 kk = k2[j];
                    r2 += (kk.x > myKey);
                    r2 += (kk.y > myKey);
                }
                if (r2 < KK) selKey[r2] = myKey;
            }
            __syncthreads();
        }

        // ---- sort the 15 selected by ascending index; emit sim_topk ----
        if (tid < KK) {
            const unsigned long long mk = selKey[tid];
            const unsigned myLow = (unsigned)mk;        // 199 - l (larger = smaller l)
            int pos = 0;
            #pragma unroll
            for (int j = 0; j < KK; ++j) pos += ((unsigned)selKey[j] > myLow);
            const int l = LL - 1 - (int)myLow;
            sortedL[pos] = l;
            out[(size_t)BB * ((KK + 1) * FF) + (size_t)b * KK + pos] = dec_f((unsigned)(mk >> 32));
        }
        if (tid == KK) sortedL[KK] = sl;
        __syncthreads();

        // ---- x_out: [16 rows x 8 feats] as float ----
        if (tid < (KK + 1) * FF) {
            const int r = tid >> 3;
            const int f = tid & 7;
            const int l = sortedL[r];
            out[(size_t)b * ((KK + 1) * FF) + tid] = (float)__ldg(xb + l * FF + f);
        }
        // loop: next iteration's first __syncthreads fences sortedL/selKey reuse
    }
}

extern "C" void kernel_launch(void* const* d_in, const int* in_sizes, int n_in,
                              void* d_out, int out_size) {
    const int*   x  = (const int*)d_in[0];   // x: [4096, 200, 8] int32
    const int*   sl = (const int*)d_in[1];   // self_loc: [4096] int32
    const float* E  = (const float*)d_in[2]; // E: [100001, 64] float32
    float* out = (float*)d_out;

    reset_ticket_kernel<<<1, 1>>>();
    search_predict_kernel<<<GRID_PERSIST, 256, SMEM_BYTES>>>(x, sl, E, out);
}

// round 11
// speedup vs baseline: 1.0862x; 1.0862x over previous
#include <cuda_runtime.h>
#include <cuda_bf16.h>
#include <math.h>

#define BB 4096
#define LL 200
#define FF 8
#define DD 64
#define KK 15
#define GRID_PERSIST 1216   // 152 SMs x 8 resident CTAs
// dynamic smem: per-row partials [200][8] float2 (each = dot/ssq over 8 floats)
#define SMEM_BYTES (LL * 8 * 8)   // 12800 B

__device__ __forceinline__ unsigned enc_f(float f) {
    unsigned u = __float_as_uint(f);
    return (u >> 31) ? ~u : (u ^ 0x80000000u);
}
__device__ __forceinline__ float dec_f(unsigned u) {
    unsigned bits = (u & 0x80000000u) ? (u ^ 0x80000000u) : ~u;
    return __uint_as_float(bits);
}

__global__ void __launch_bounds__(256, 8) search_predict_kernel(
    const int* __restrict__ x,        // [B, L, F] int32
    const int* __restrict__ self_loc, // [B] int32
    const float* __restrict__ E,      // [NFEAT+1, D] float32
    float* __restrict__ out)          // [B*16*8] x_out-as-float, then [B*15] sim_topk
{
    extern __shared__ __align__(16) float partials[];   // [200][8] float2, rot-swizzled

    __shared__ __align__(16) float4 selfv[16];          // self embedding row
    __shared__ int catS[LL];
    __shared__ __align__(16) unsigned long long keys[224];
    __shared__ __align__(16) unsigned simk[224];
    __shared__ unsigned long long selKey[KK];
    __shared__ int sortedL[KK + 1];
    __shared__ float invns;
    __shared__ int bad;

    const int tid  = threadIdx.x;
    const int warp = tid >> 5;

    for (int b = blockIdx.x; b < BB; b += GRID_PERSIST) {
        const int* xb = x + (size_t)b * (LL * FF);
        const int sl = __ldg(self_loc + b);

        if (tid == 0) bad = 0;
        // catS for rows <= sl only; warp 7 loads self row + precomputes inv-norm.
        // (The __syncthreads below also fences prev iteration's sortedL readers —
        //  this phase writes only catS/selfv/invns/bad, disjoint from sortedL.)
        if (tid <= sl) catS[tid] = __ldg(xb + tid * FF + 5);
        if (warp == 7) {
            const int hl = tid & 15;
            if ((tid & 31) < 16) {
                const int cs = __ldg(xb + sl * FF + 5);
                selfv[hl] = __ldg(reinterpret_cast<const float4*>(E + (size_t)cs * DD) + hl);
            }
            __syncwarp();
            const float4 s = selfv[hl];                   // lanes 16-31 mirror 0-15
            float q = s.x * s.x + s.y * s.y + s.z * s.z + s.w * s.w;
            q += __shfl_xor_sync(0xffffffffu, q, 8);
            q += __shfl_xor_sync(0xffffffffu, q, 4);
            q += __shfl_xor_sync(0xffffffffu, q, 2);
            q += __shfl_xor_sync(0xffffffffu, q, 1);
            if (tid == 224) invns = rsqrtf(q + 1e-8f);
        }
        __syncthreads();

        // ---- Phase A: fused gather + partials, ONLY rows l <= sl ----
        {
            const int rg = tid >> 3;          // row within 32-row tile
            const int j8 = tid & 7;           // owns float4 slices j8 and j8+8
            const float4 sa = selfv[j8];
            const float4 sb = selfv[j8 + 8];
            #pragma unroll
            for (int it = 0; it < 7; ++it) {
                const int l = it * 32 + rg;
                if (l <= sl) {                // warp-uniform except one boundary warp
                    const int c = catS[l];
                    const float4* rp = reinterpret_cast<const float4*>(E + (size_t)c * DD);
                    const float4 va = __ldg(rp + j8);
                    const float4 vb = __ldg(rp + j8 + 8);
                    const float dp = va.x*sa.x + va.y*sa.y + va.z*sa.z + va.w*sa.w
                                   + vb.x*sb.x + vb.y*sb.y + vb.z*sb.z + vb.w*sb.w;
                    const float qp = va.x*va.x + va.y*va.y + va.z*va.z + va.w*va.w
                                   + vb.x*vb.x + vb.y*vb.y + vb.z*vb.z + vb.w*vb.w;
                    // rotation swizzle: partial j8 of row l -> 16B chunk ((j8>>1)+(l>>1))&3
                    const int byteoff = l * 64 + ((((j8 >> 1) + (l >> 1)) & 3) << 4)
                                      + ((j8 & 1) << 3);
                    *reinterpret_cast<float2*>(reinterpret_cast<char*>(partials) + byteoff)
                        = make_float2(dp, qp);
                }
            }
        }
        __syncthreads();

        // ---- Phase B: thread-per-row reduction, only rows <= sl ----
        float dot = 0.f, ssq = 0.f;
        if (tid <= sl) {
            const char* base = reinterpret_cast<const char*>(partials) + tid * 64;
            const int rot = (tid >> 1) & 3;
            #pragma unroll
            for (int k = 0; k < 4; ++k) {     // logical chunk order fixed (bit-exact dups)
                const float4 c = *reinterpret_cast<const float4*>(base + (((k + rot) & 3) << 4));
                dot += c.x + c.z;
                ssq += c.y + c.w;
            }
        }
        const float sim = (tid < sl) ? dot * rsqrtf(ssq + 1e-8f) * invns : -2.0f;
        const unsigned e = enc_f(sim);
        const unsigned long long myKey =
            ((unsigned long long)e << 32) | (unsigned)(LL - 1 - tid);
        if (tid < 224) { keys[tid] = myKey; simk[tid] = e; }   // 200..223 pad, inert
        __syncthreads();

        // ---- rank-select among the first sl keys only ----
        int rank = LL;
        if (tid < sl) {
            int r = 0;
            const uint4* p = reinterpret_cast<const uint4*>(simk);
            const int nj = (sl + 3) >> 2;
            for (int j = 0; j < nj; ++j) {            // broadcast LDS.128
                const uint4 k = p[j];
                r += (k.x > e);
                r += (k.y > e);
                r += (k.z > e);
                r += (k.w > e);
            }
            rank = r;
            if (r < KK) selKey[r] = myKey;
        }
        __syncthreads();

        // tie inside top-K -> two threads shared a slot -> loser flags; rare
        if (rank < KK && selKey[rank] != myKey) bad = 1;
        __syncthreads();

        if (bad) {   // exact 64-bit tie-aware recount (keys strictly unique)
            if (tid < sl) {
                int r2 = 0;
                const ulonglong2* k2 = reinterpret_cast<const ulonglong2*>(keys);
                const int nj2 = (sl + 1) >> 1;
                for (int j = 0; j < nj2; ++j) {
                    const ulonglong2 kk = k2[j];
                    r2 += (kk.x > myKey);
                    r2 += (kk.y > myKey);
                }
                if (r2 < KK) selKey[r2] = myKey;
            }
            __syncthreads();
        }

        // ---- sort the 15 selected by ascending index; emit sim_topk ----
        if (tid < KK) {
            const unsigned long long mk = selKey[tid];
            const unsigned myLow = (unsigned)mk;        // 199 - l (larger = smaller l)
            int pos = 0;
            #pragma unroll
            for (int j = 0; j < KK; ++j) pos += ((unsigned)selKey[j] > myLow);
            const int l = LL - 1 - (int)myLow;
            sortedL[pos] = l;
            out[(size_t)BB * ((KK + 1) * FF) + (size_t)b * KK + pos] = dec_f((unsigned)(mk >> 32));
        }
        if (tid == KK) sortedL[KK] = sl;
        __syncthreads();

        // ---- x_out: [16 rows x 8 feats] as float ----
        if (tid < (KK + 1) * FF) {
            const int r = tid >> 3;
            const int f = tid & 7;
            const int l = sortedL[r];
            out[(size_t)b * ((KK + 1) * FF) + tid] = (float)__ldg(xb + l * FF + f);
        }
        __syncthreads();   // sortedL read-complete before next iteration's writes
    }
}

extern "C" void kernel_launch(void* const* d_in, const int* in_sizes, int n_in,
                              void* d_out, int out_size) {
    const int*   x  = (const int*)d_in[0];   // x: [4096, 200, 8] int32
    const int*   sl = (const int*)d_in[1];   // self_loc: [4096] int32
    const float* E  = (const float*)d_in[2]; // E: [100001, 64] float32
    float* out = (float*)d_out;

    search_predict_kernel<<<GRID_PERSIST, 256, SMEM_BYTES>>>(x, sl, E, out);
}

// round 12
// speedup vs baseline: 1.1616x; 1.0694x over previous
#include <cuda_runtime.h>
#include <cuda_bf16.h>
#include <math.h>

#define BB 4096
#define LL 200
#define FF 8
#define DD 64
#define KK 15
// dynamic smem: per-row partials [200][8] float2 (each = dot/ssq over 8 floats)
#define SMEM_BYTES (LL * 8 * 8)   // 12800 B

__device__ __forceinline__ unsigned enc_f(float f) {
    unsigned u = __float_as_uint(f);
    return (u >> 31) ? ~u : (u ^ 0x80000000u);
}
__device__ __forceinline__ float dec_f(unsigned u) {
    unsigned bits = (u & 0x80000000u) ? (u ^ 0x80000000u) : ~u;
    return __uint_as_float(bits);
}

__global__ void __launch_bounds__(256) search_predict_kernel(
    const int* __restrict__ x,        // [B, L, F] int32
    const int* __restrict__ self_loc, // [B] int32
    const float* __restrict__ E,      // [NFEAT+1, D] float32
    float* __restrict__ out)          // [B*16*8] x_out-as-float, then [B*15] sim_topk
{
    extern __shared__ __align__(16) float partials[];   // [200][8] float2, rot-swizzled

    __shared__ __align__(16) float4 selfv[16];          // self embedding row
    __shared__ int catS[LL];
    __shared__ __align__(16) unsigned simk[224];        // 32-bit encoded sims
    __shared__ unsigned long long selKey[KK];
    __shared__ int sortedL[KK + 1];
    __shared__ float invns;

    const int b    = blockIdx.x;
    const int tid  = threadIdx.x;
    const int warp = tid >> 5;

    const int* xb = x + (size_t)b * (LL * FF);
    const int sl = __ldg(self_loc + b);

    // catS for rows <= sl only; warp 7 loads self row + precomputes inv-norm
    if (tid <= sl) catS[tid] = __ldg(xb + tid * FF + 5);
    if (warp == 7) {
        const int hl = tid & 15;
        if ((tid & 31) < 16) {
            const int cs = __ldg(xb + sl * FF + 5);
            selfv[hl] = __ldg(reinterpret_cast<const float4*>(E + (size_t)cs * DD) + hl);
        }
        __syncwarp();
        const float4 s = selfv[hl];                       // lanes 16-31 mirror 0-15
        float q = s.x * s.x + s.y * s.y + s.z * s.z + s.w * s.w;
        q += __shfl_xor_sync(0xffffffffu, q, 8);
        q += __shfl_xor_sync(0xffffffffu, q, 4);
        q += __shfl_xor_sync(0xffffffffu, q, 2);
        q += __shfl_xor_sync(0xffffffffu, q, 1);
        if (tid == 224) invns = rsqrtf(q + 1e-8f);
    }
    __syncthreads();

    // ---- Phase A: fused gather + partials, ONLY rows l <= sl ----
    {
        const int rg = tid >> 3;          // row within 32-row tile
        const int j8 = tid & 7;           // owns float4 slices j8 and j8+8
        const float4 sa = selfv[j8];
        const float4 sb = selfv[j8 + 8];
        #pragma unroll
        for (int it = 0; it < 7; ++it) {
            const int l = it * 32 + rg;
            if (l <= sl) {                // warp-uniform except one boundary warp
                const int c = catS[l];
                const float4* rp = reinterpret_cast<const float4*>(E + (size_t)c * DD);
                const float4 va = __ldg(rp + j8);
                const float4 vb = __ldg(rp + j8 + 8);
                const float dp = va.x*sa.x + va.y*sa.y + va.z*sa.z + va.w*sa.w
                               + vb.x*sb.x + vb.y*sb.y + vb.z*sb.z + vb.w*sb.w;
                const float qp = va.x*va.x + va.y*va.y + va.z*va.z + va.w*va.w
                               + vb.x*vb.x + vb.y*vb.y + vb.z*vb.z + vb.w*vb.w;
                // rotation swizzle: partial j8 of row l -> 16B chunk ((j8>>1)+(l>>1))&3
                const int byteoff = l * 64 + ((((j8 >> 1) + (l >> 1)) & 3) << 4)
                                  + ((j8 & 1) << 3);
                *reinterpret_cast<float2*>(reinterpret_cast<char*>(partials) + byteoff)
                    = make_float2(dp, qp);
            }
        }
    }
    __syncthreads();

    // ---- Phase B: thread-per-row reduction, only rows <= sl ----
    float dot = 0.f, ssq = 0.f;
    if (tid <= sl) {
        const char* base = reinterpret_cast<const char*>(partials) + tid * 64;
        const int rot = (tid >> 1) & 3;
        #pragma unroll
        for (int k = 0; k < 4; ++k) {     // logical chunk order fixed (bit-exact dups)
            const float4 c = *reinterpret_cast<const float4*>(base + (((k + rot) & 3) << 4));
            dot += c.x + c.z;
            ssq += c.y + c.w;
        }
    }
    const float sim = (tid < sl) ? dot * rsqrtf(ssq + 1e-8f) * invns : -2.0f;
    const unsigned e = enc_f(sim);
    const unsigned long long myKey =
        ((unsigned long long)e << 32) | (unsigned)(LL - 1 - tid);
    if (tid < 224) simk[tid] = e;          // 200..223 pad = enc(-2), inert
    __syncthreads();

    // ---- rank-select among the first sl keys only (32-bit fast path) ----
    int rank = LL;
    if (tid < sl) {
        int r = 0;
        const uint4* p = reinterpret_cast<const uint4*>(simk);
        const int nj = (sl + 3) >> 2;
        for (int j = 0; j < nj; ++j) {            // broadcast LDS.128
            const uint4 k = p[j];
            r += (k.x > e);
            r += (k.y > e);
            r += (k.z > e);
            r += (k.w > e);
        }
        rank = r;
        if (r < KK) selKey[r] = myKey;
    }
    __syncthreads();                               // publish selKey

    // tie inside top-K -> two threads shared a slot -> loser detects; rare
    const int pred = (rank < KK) && (selKey[rank] != myKey);
    if (__syncthreads_or(pred)) {
        // exact tie-aware recount; key_j > myKey  <=>  ej > e || (ej == e && j < tid)
        if (tid < sl) {
            int r2 = 0;
            for (int j = 0; j < sl; ++j) {
                const unsigned ej = simk[j];
                r2 += (ej > e) || (ej == e && j < tid);
            }
            if (r2 < KK) selKey[r2] = myKey;
        }
        __syncthreads();
    }

    // ---- sort the 15 selected by ascending index; emit sim_topk ----
    if (tid < KK) {
        const unsigned long long mk = selKey[tid];
        const unsigned myLow = (unsigned)mk;        // 199 - l (larger = smaller l)
        int pos = 0;
        #pragma unroll
        for (int j = 0; j < KK; ++j) pos += ((unsigned)selKey[j] > myLow);
        const int l = LL - 1 - (int)myLow;
        sortedL[pos] = l;
        out[(size_t)BB * ((KK + 1) * FF) + (size_t)b * KK + pos] = dec_f((unsigned)(mk >> 32));
    }
    if (tid == KK) sortedL[KK] = sl;
    __syncthreads();

    // ---- x_out: [16 rows x 8 feats] as float ----
    if (tid < (KK + 1) * FF) {
        const int r = tid >> 3;
        const int f = tid & 7;
        const int l = sortedL[r];
        out[(size_t)b * ((KK + 1) * FF) + tid] = (float)__ldg(xb + l * FF + f);
    }
}

extern "C" void kernel_launch(void* const* d_in, const int* in_sizes, int n_in,
                              void* d_out, int out_size) {
    const int*   x  = (const int*)d_in[0];   // x: [4096, 200, 8] int32
    const int*   sl = (const int*)d_in[1];   // self_loc: [4096] int32
    const float* E  = (const float*)d_in[2]; // E: [100001, 64] float32
    float* out = (float*)d_out;

    search_predict_kernel<<<BB, 256, SMEM_BYTES>>>(x, sl, E, out);
}